// round 8
// baseline (speedup 1.0000x reference)
#include <cuda_runtime.h>
#include <cuda_bf16.h>
#include <math.h>
#include <stdint.h>

// ---------------- problem constants ----------------
#define BATCH 4
#define SEQ   2048
#define DIM   512
#define NHEAD 8
#define HDIM  64
#define FFN   2048
#define MTOT  (BATCH * SEQ)          // 8192 rows
#define QKVW  (3 * DIM)              // 1536

// ---------------- scratch (no allocation allowed) ----------------
__device__ float g_qkv [MTOT * QKVW];      // fused q|k|v
__device__ float g_att [MTOT * DIM];
__device__ float g_y1  [MTOT * DIM];
__device__ float g_x1  [MTOT * DIM];
__device__ float g_h   [MTOT * FFN];
__device__ float g_y2  [MTOT * DIM];

// ---------------- helpers ----------------
__device__ __forceinline__ uint32_t f2tf(float x) {
    uint32_t r;
    asm("cvt.rna.tf32.f32 %0, %1;" : "=r"(r) : "f"(x));
    return r;
}
__device__ __forceinline__ float gelu_exact(float v) {
    return 0.5f * v * (1.0f + erff(v * 0.70710678118654752f));
}
__device__ __forceinline__ void mma16n8k8(float* c, const uint32_t* a, const uint32_t* b) {
    asm volatile(
        "mma.sync.aligned.m16n8k8.row.col.f32.tf32.tf32.f32 "
        "{%0,%1,%2,%3}, {%4,%5,%6,%7}, {%8,%9}, {%0,%1,%2,%3};"
        : "+f"(c[0]), "+f"(c[1]), "+f"(c[2]), "+f"(c[3])
        : "r"(a[0]), "r"(a[1]), "r"(a[2]), "r"(a[3]), "r"(b[0]), "r"(b[1]));
}

// ---------------- tf32 mma.sync GEMM ----------------
// C[128-block rows, 128-block cols] = A[M,K] @ B[K,ldb](col block) + bias (+res/gelu)
// 256 threads = 8 warps (2 x 4), warp tile 64x32, mma m16n8k8.
#define LDA 136
#define LDB 136
#define GEMM_SMEM ((32 * LDA + 32 * LDB) * 4)

template<int EPI>
__device__ __forceinline__ void mma_gemm_body(
    const float* __restrict__ A,
    const float* __restrict__ B, int ldb, int bcol,
    const float* __restrict__ biasBlk,       // pre-offset to this col block
    const float* __restrict__ res,
    float* __restrict__ C, int ldc, int ccol,
    int K)
{
    extern __shared__ uint32_t smu[];
    uint32_t* As = smu;                 // [32][LDA]  k-major, m fast
    uint32_t* Bs = smu + 32 * LDA;      // [32][LDB]  k-major, n fast

    const int tid  = threadIdx.x;
    const int lane = tid & 31;
    const int wid  = tid >> 5;
    const int gid  = lane >> 2;
    const int tig  = lane & 3;
    const int rowBase = blockIdx.y * 128;
    const int mb = (wid & 1) * 64;
    const int nb = (wid >> 1) * 32;

    // cooperative load mapping
    const int ar  = tid >> 1;              // 0..127  (A row in tile)
    const int akq = (tid & 1) * 16;        // 0 / 16  (A k offset)
    const int bkr = tid >> 3;              // 0..31   (B k row)
    const int bc  = (tid & 7) * 16;        // B n offset

    float acc[4][4][4];
    #pragma unroll
    for (int i = 0; i < 4; i++)
        #pragma unroll
        for (int j = 0; j < 4; j++)
            #pragma unroll
            for (int e = 0; e < 4; e++) acc[i][j][e] = 0.0f;

    const float* apB = A + (size_t)(rowBase + ar) * K + akq;
    const float* bpB = B + (size_t)bkr * ldb + bcol + bc;

    const int NC = K >> 5;
    for (int c = 0; c < NC; c++) {
        __syncthreads();
        {   // A: 128x32, store transposed As[k][m] with tf32 cvt
            const float* ap = apB + c * 32;
            #pragma unroll
            for (int i = 0; i < 4; i++) {
                float4 v = *(const float4*)(ap + i * 4);
                As[(akq + i * 4 + 0) * LDA + ar] = f2tf(v.x);
                As[(akq + i * 4 + 1) * LDA + ar] = f2tf(v.y);
                As[(akq + i * 4 + 2) * LDA + ar] = f2tf(v.z);
                As[(akq + i * 4 + 3) * LDA + ar] = f2tf(v.w);
            }
            // B: 32x128 direct (row-major W[K][N]) with tf32 cvt
            const float* bp = bpB + (size_t)(c * 32) * ldb;
            #pragma unroll
            for (int i = 0; i < 4; i++) {
                float4 v = *(const float4*)(bp + i * 4);
                uint4 u = make_uint4(f2tf(v.x), f2tf(v.y), f2tf(v.z), f2tf(v.w));
                *(uint4*)&Bs[bkr * LDB + bc + i * 4] = u;
            }
        }
        __syncthreads();

        #pragma unroll
        for (int k8 = 0; k8 < 4; k8++) {
            const int r0 = k8 * 8 + tig;
            const int r1 = r0 + 4;
            uint32_t a[4][4], b[4][2];
            #pragma unroll
            for (int mt = 0; mt < 4; mt++) {
                const int cm = mb + mt * 16 + gid;
                a[mt][0] = As[r0 * LDA + cm];
                a[mt][1] = As[r0 * LDA + cm + 8];
                a[mt][2] = As[r1 * LDA + cm];
                a[mt][3] = As[r1 * LDA + cm + 8];
            }
            #pragma unroll
            for (int nt = 0; nt < 4; nt++) {
                const int cn = nb + nt * 8 + gid;
                b[nt][0] = Bs[r0 * LDB + cn];
                b[nt][1] = Bs[r1 * LDB + cn];
            }
            #pragma unroll
            for (int mt = 0; mt < 4; mt++)
                #pragma unroll
                for (int nt = 0; nt < 4; nt++)
                    mma16n8k8(acc[mt][nt], a[mt], b[nt]);
        }
    }

    // epilogue
    #pragma unroll
    for (int mt = 0; mt < 4; mt++) {
        const int row0 = rowBase + mb + mt * 16 + gid;
        const int row1 = row0 + 8;
        #pragma unroll
        for (int nt = 0; nt < 4; nt++) {
            const int jc  = nb + nt * 8 + tig * 2;  // local col in 128-block
            const int col = ccol + jc;
            const float b0 = biasBlk[jc], b1 = biasBlk[jc + 1];
            float v0 = acc[mt][nt][0] + b0;
            float v1 = acc[mt][nt][1] + b1;
            float v2 = acc[mt][nt][2] + b0;
            float v3 = acc[mt][nt][3] + b1;
            if (EPI == 1) {
                const float* rp0 = res + (size_t)row0 * ldc + col;
                const float* rp1 = res + (size_t)row1 * ldc + col;
                v0 += rp0[0]; v1 += rp0[1];
                v2 += rp1[0]; v3 += rp1[1];
            }
            if (EPI == 2) {
                v0 = gelu_exact(v0); v1 = gelu_exact(v1);
                v2 = gelu_exact(v2); v3 = gelu_exact(v3);
            }
            *(float2*)(C + (size_t)row0 * ldc + col) = make_float2(v0, v1);
            *(float2*)(C + (size_t)row1 * ldc + col) = make_float2(v2, v3);
        }
    }
}

template<int EPI>
__global__ __launch_bounds__(256) void gemm_mma(
    const float* __restrict__ A, const float* __restrict__ B, int ldb,
    const float* __restrict__ bias, const float* __restrict__ res,
    float* __restrict__ C, int ldc, int K)
{
    const int bcol = blockIdx.x * 128;
    mma_gemm_body<EPI>(A, B, ldb, bcol, bias + bcol, res, C, ldc, bcol, K);
}

// fused QKV: blockIdx.x in [0,12): sel = bx>>2 picks wq/wk/wv, (bx&3) picks col block
__global__ __launch_bounds__(256) void qkv_mma(
    const float* __restrict__ x,
    const float* __restrict__ wq, const float* __restrict__ bq,
    const float* __restrict__ wk, const float* __restrict__ bk,
    const float* __restrict__ wv, const float* __restrict__ bv,
    float* __restrict__ qkv)
{
    const int bx  = blockIdx.x;
    const int sel = bx >> 2;
    const float* W  = (sel == 0) ? wq : (sel == 1) ? wk : wv;
    const float* bi = (sel == 0) ? bq : (sel == 1) ? bk : bv;
    const int bcol = (bx & 3) * 128;
    mma_gemm_body<0>(x, W, DIM, bcol, bi + bcol, nullptr, qkv, QKVW, bx * 128, DIM);
}

// ---------------- flash attention (fp32), AQ=64, AK=64 ----------------
#define AQ 64
#define AK 64
#define PAD 4
#define AST (AK + PAD)   // 68

__global__ __launch_bounds__(256) void attn_kernel(
    const float* __restrict__ QKV, float* __restrict__ O)
{
    extern __shared__ float sm[];
    float* Qs = sm;                    // [HDIM][AST]
    float* Ks = Qs + HDIM * AST;       // [HDIM][AST]
    float* Vs = Ks + HDIM * AST;       // [AK][AST]
    float* Ss = Vs + AK * AST;         // [AQ][AST]
    float* mrow = Ss + AQ * AST;
    float* lrow = mrow + AQ;
    float* arow = lrow + AQ;

#define QS(d,qq) Qs[(d)*AST+(qq)]
#define KS(d,kk) Ks[(d)*AST+(kk)]
#define VS(kk,d) Vs[(kk)*AST+(d)]
#define SS(qq,kk) Ss[(qq)*AST+(kk)]

    const int tid = threadIdx.x;
    const int tx  = tid & 15;
    const int ty  = tid >> 4;
    const int lane = tid & 31;
    const int d0   = (tid >> 5) * 8;
    const int bh = blockIdx.y;
    const int b  = bh >> 3;
    const int h  = bh & 7;
    const int q0 = blockIdx.x * AQ;
    const float scale = 0.125f;
    const int LD = QKVW;               // fused qkv row stride

    const float* Qb = QKV + (size_t)b * SEQ * LD + (size_t)h * HDIM;
    const float* Kb = Qb + DIM;
    const float* Vb = Qb + 2 * DIM;

    {
        const float* p0 = Qb + (size_t)(q0 + lane) * LD + d0;
        const float* p1 = Qb + (size_t)(q0 + lane + 32) * LD + d0;
        float4 u0 = *(const float4*)p0;
        float4 u1 = *(const float4*)(p0 + 4);
        float4 u2 = *(const float4*)p1;
        float4 u3 = *(const float4*)(p1 + 4);
        QS(d0 + 0, lane) = u0.x; QS(d0 + 1, lane) = u0.y;
        QS(d0 + 2, lane) = u0.z; QS(d0 + 3, lane) = u0.w;
        QS(d0 + 4, lane) = u1.x; QS(d0 + 5, lane) = u1.y;
        QS(d0 + 6, lane) = u1.z; QS(d0 + 7, lane) = u1.w;
        QS(d0 + 0, lane + 32) = u2.x; QS(d0 + 1, lane + 32) = u2.y;
        QS(d0 + 2, lane + 32) = u2.z; QS(d0 + 3, lane + 32) = u2.w;
        QS(d0 + 4, lane + 32) = u3.x; QS(d0 + 5, lane + 32) = u3.y;
        QS(d0 + 6, lane + 32) = u3.z; QS(d0 + 7, lane + 32) = u3.w;
    }
    if (tid < AQ) { mrow[tid] = -1e30f; lrow[tid] = 0.0f; }

    float o[4][4] = {};

    for (int t = 0; t < SEQ / AK; t++) {
        __syncthreads();
        {
            const float* kp0 = Kb + (size_t)(t * AK + lane) * LD + d0;
            const float* kp1 = kp0 + (size_t)32 * LD;
            float4 k0v = *(const float4*)kp0;
            float4 k1v = *(const float4*)(kp0 + 4);
            float4 k2v = *(const float4*)kp1;
            float4 k3v = *(const float4*)(kp1 + 4);
            KS(d0 + 0, lane) = k0v.x; KS(d0 + 1, lane) = k0v.y;
            KS(d0 + 2, lane) = k0v.z; KS(d0 + 3, lane) = k0v.w;
            KS(d0 + 4, lane) = k1v.x; KS(d0 + 5, lane) = k1v.y;
            KS(d0 + 6, lane) = k1v.z; KS(d0 + 7, lane) = k1v.w;
            KS(d0 + 0, lane + 32) = k2v.x; KS(d0 + 1, lane + 32) = k2v.y;
            KS(d0 + 2, lane + 32) = k2v.z; KS(d0 + 3, lane + 32) = k2v.w;
            KS(d0 + 4, lane + 32) = k3v.x; KS(d0 + 5, lane + 32) = k3v.y;
            KS(d0 + 6, lane + 32) = k3v.z; KS(d0 + 7, lane + 32) = k3v.w;

            const float* vp0 = Vb + (size_t)(t * AK + lane) * LD + d0;
            const float* vp1 = vp0 + (size_t)32 * LD;
            float4 v0v = *(const float4*)vp0;
            float4 v1v = *(const float4*)(vp0 + 4);
            float4 v2v = *(const float4*)vp1;
            float4 v3v = *(const float4*)(vp1 + 4);
            *(float4*)&VS(lane, d0)          = v0v;
            *(float4*)&VS(lane, d0 + 4)      = v1v;
            *(float4*)&VS(lane + 32, d0)     = v2v;
            *(float4*)&VS(lane + 32, d0 + 4) = v3v;
        }
        __syncthreads();

        float s[4][4] = {};
        #pragma unroll 16
        for (int d = 0; d < HDIM; d++) {
            float4 aq = *(const float4*)&QS(d, ty * 4);
            float4 bk = *(const float4*)&KS(d, tx * 4);
            s[0][0] = fmaf(aq.x, bk.x, s[0][0]); s[0][1] = fmaf(aq.x, bk.y, s[0][1]);
            s[0][2] = fmaf(aq.x, bk.z, s[0][2]); s[0][3] = fmaf(aq.x, bk.w, s[0][3]);
            s[1][0] = fmaf(aq.y, bk.x, s[1][0]); s[1][1] = fmaf(aq.y, bk.y, s[1][1]);
            s[1][2] = fmaf(aq.y, bk.z, s[1][2]); s[1][3] = fmaf(aq.y, bk.w, s[1][3]);
            s[2][0] = fmaf(aq.z, bk.x, s[2][0]); s[2][1] = fmaf(aq.z, bk.y, s[2][1]);
            s[2][2] = fmaf(aq.z, bk.z, s[2][2]); s[2][3] = fmaf(aq.z, bk.w, s[2][3]);
            s[3][0] = fmaf(aq.w, bk.x, s[3][0]); s[3][1] = fmaf(aq.w, bk.y, s[3][1]);
            s[3][2] = fmaf(aq.w, bk.z, s[3][2]); s[3][3] = fmaf(aq.w, bk.w, s[3][3]);
        }
        #pragma unroll
        for (int i = 0; i < 4; i++) {
            float4 w = make_float4(s[i][0] * scale, s[i][1] * scale,
                                   s[i][2] * scale, s[i][3] * scale);
            *(float4*)&SS(ty * 4 + i, tx * 4) = w;
        }
        __syncthreads();

        {
            const int r = tid >> 2;
            const int p = tid & 3;
            float* row = &SS(r, p * 16);
            float4 e0 = *(float4*)(row + 0);
            float4 e1 = *(float4*)(row + 4);
            float4 e2 = *(float4*)(row + 8);
            float4 e3 = *(float4*)(row + 12);
            const float mold = mrow[r];
            float mx = fmaxf(fmaxf(fmaxf(e0.x, e0.y), fmaxf(e0.z, e0.w)),
                             fmaxf(fmaxf(e1.x, e1.y), fmaxf(e1.z, e1.w)));
            mx = fmaxf(mx, fmaxf(fmaxf(fmaxf(e2.x, e2.y), fmaxf(e2.z, e2.w)),
                                 fmaxf(fmaxf(e3.x, e3.y), fmaxf(e3.z, e3.w))));
            mx = fmaxf(mx, __shfl_xor_sync(0xffffffffu, mx, 1));
            mx = fmaxf(mx, __shfl_xor_sync(0xffffffffu, mx, 2));
            mx = fmaxf(mx, mold);
            e0.x = __expf(e0.x - mx); e0.y = __expf(e0.y - mx);
            e0.z = __expf(e0.z - mx); e0.w = __expf(e0.w - mx);
            e1.x = __expf(e1.x - mx); e1.y = __expf(e1.y - mx);
            e1.z = __expf(e1.z - mx); e1.w = __expf(e1.w - mx);
            e2.x = __expf(e2.x - mx); e2.y = __expf(e2.y - mx);
            e2.z = __expf(e2.z - mx); e2.w = __expf(e2.w - mx);
            e3.x = __expf(e3.x - mx); e3.y = __expf(e3.y - mx);
            e3.z = __expf(e3.z - mx); e3.w = __expf(e3.w - mx);
            *(float4*)(row + 0)  = e0;
            *(float4*)(row + 4)  = e1;
            *(float4*)(row + 8)  = e2;
            *(float4*)(row + 12) = e3;
            float sum = (e0.x + e0.y + e0.z + e0.w) + (e1.x + e1.y + e1.z + e1.w)
                      + (e2.x + e2.y + e2.z + e2.w) + (e3.x + e3.y + e3.z + e3.w);
            sum += __shfl_xor_sync(0xffffffffu, sum, 1);
            sum += __shfl_xor_sync(0xffffffffu, sum, 2);
            if (p == 0) {
                const float al = __expf(mold - mx);
                arow[r] = al;
                lrow[r] = lrow[r] * al + sum;
                mrow[r] = mx;
            }
        }
        __syncthreads();

        {
            const float al0 = arow[ty * 4 + 0];
            const float al1 = arow[ty * 4 + 1];
            const float al2 = arow[ty * 4 + 2];
            const float al3 = arow[ty * 4 + 3];
            #pragma unroll
            for (int j = 0; j < 4; j++) {
                o[0][j] *= al0; o[1][j] *= al1; o[2][j] *= al2; o[3][j] *= al3;
            }
            #pragma unroll 16
            for (int kk = 0; kk < AK; kk++) {
                const float a0 = SS(ty * 4 + 0, kk);
                const float a1 = SS(ty * 4 + 1, kk);
                const float a2 = SS(ty * 4 + 2, kk);
                const float a3 = SS(ty * 4 + 3, kk);
                float4 bv = *(const float4*)&VS(kk, tx * 4);
                o[0][0] = fmaf(a0, bv.x, o[0][0]); o[0][1] = fmaf(a0, bv.y, o[0][1]);
                o[0][2] = fmaf(a0, bv.z, o[0][2]); o[0][3] = fmaf(a0, bv.w, o[0][3]);
                o[1][0] = fmaf(a1, bv.x, o[1][0]); o[1][1] = fmaf(a1, bv.y, o[1][1]);
                o[1][2] = fmaf(a1, bv.z, o[1][2]); o[1][3] = fmaf(a1, bv.w, o[1][3]);
                o[2][0] = fmaf(a2, bv.x, o[2][0]); o[2][1] = fmaf(a2, bv.y, o[2][1]);
                o[2][2] = fmaf(a2, bv.z, o[2][2]); o[2][3] = fmaf(a2, bv.w, o[2][3]);
                o[3][0] = fmaf(a3, bv.x, o[3][0]); o[3][1] = fmaf(a3, bv.y, o[3][1]);
                o[3][2] = fmaf(a3, bv.z, o[3][2]); o[3][3] = fmaf(a3, bv.w, o[3][3]);
            }
        }
    }

    const float inv0 = 1.0f / lrow[ty * 4 + 0];
    const float inv1 = 1.0f / lrow[ty * 4 + 1];
    const float inv2 = 1.0f / lrow[ty * 4 + 2];
    const float inv3 = 1.0f / lrow[ty * 4 + 3];
    float* Ob = O + (size_t)b * SEQ * DIM + (size_t)h * HDIM;
    {
        float4 w0 = make_float4(o[0][0] * inv0, o[0][1] * inv0, o[0][2] * inv0, o[0][3] * inv0);
        float4 w1 = make_float4(o[1][0] * inv1, o[1][1] * inv1, o[1][2] * inv1, o[1][3] * inv1);
        float4 w2 = make_float4(o[2][0] * inv2, o[2][1] * inv2, o[2][2] * inv2, o[2][3] * inv2);
        float4 w3 = make_float4(o[3][0] * inv3, o[3][1] * inv3, o[3][2] * inv3, o[3][3] * inv3);
        *(float4*)(Ob + (size_t)(q0 + ty * 4 + 0) * DIM + tx * 4) = w0;
        *(float4*)(Ob + (size_t)(q0 + ty * 4 + 1) * DIM + tx * 4) = w1;
        *(float4*)(Ob + (size_t)(q0 + ty * 4 + 2) * DIM + tx * 4) = w2;
        *(float4*)(Ob + (size_t)(q0 + ty * 4 + 3) * DIM + tx * 4) = w3;
    }
}

#define ATTN_SMEM ((2 * HDIM * AST + AK * AST + AQ * AST + 3 * AQ) * (int)sizeof(float))

// ---------------- layernorm ----------------
__global__ __launch_bounds__(256) void ln_kernel(
    const float* __restrict__ x, const float* __restrict__ g,
    const float* __restrict__ be, float* __restrict__ out)
{
    const int row = blockIdx.x;
    const int t = threadIdx.x;
    const float* xr = x + (size_t)row * DIM;
    float v0 = xr[t], v1 = xr[t + 256];
    float s = v0 + v1, sq = v0 * v0 + v1 * v1;
    #pragma unroll
    for (int o = 16; o > 0; o >>= 1) {
        s  += __shfl_xor_sync(0xffffffffu, s, o);
        sq += __shfl_xor_sync(0xffffffffu, sq, o);
    }
    __shared__ float ps[8], pq[8];
    __shared__ float mu_s, inv_s;
    if ((t & 31) == 0) { ps[t >> 5] = s; pq[t >> 5] = sq; }
    __syncthreads();
    if (t == 0) {
        float S = 0.0f, Qq = 0.0f;
        #pragma unroll
        for (int i = 0; i < 8; i++) { S += ps[i]; Qq += pq[i]; }
        float mu = S * (1.0f / DIM);
        float var = Qq * (1.0f / DIM) - mu * mu;
        mu_s = mu;
        inv_s = rsqrtf(var + 1e-5f);
    }
    __syncthreads();
    float mu = mu_s, inv = inv_s;
    out[(size_t)row * DIM + t]       = (v0 - mu) * inv * g[t]       + be[t];
    out[(size_t)row * DIM + t + 256] = (v1 - mu) * inv * g[t + 256] + be[t + 256];
}

// ---------------- launch ----------------
extern "C" void kernel_launch(void* const* d_in, const int* in_sizes, int n_in,
                              void* d_out, int out_size)
{
    const float* x   = (const float*)d_in[0];
    const float* wq  = (const float*)d_in[1];
    const float* bq  = (const float*)d_in[2];
    const float* wk  = (const float*)d_in[3];
    const float* bk  = (const float*)d_in[4];
    const float* wv  = (const float*)d_in[5];
    const float* bv  = (const float*)d_in[6];
    const float* wo  = (const float*)d_in[7];
    const float* bo  = (const float*)d_in[8];
    const float* w1  = (const float*)d_in[9];
    const float* b1  = (const float*)d_in[10];
    const float* w2  = (const float*)d_in[11];
    const float* b2  = (const float*)d_in[12];
    const float* g1  = (const float*)d_in[13];
    const float* be1 = (const float*)d_in[14];
    const float* g2  = (const float*)d_in[15];
    const float* be2 = (const float*)d_in[16];
    float* out = (float*)d_out;

    float *qkv, *att, *y1, *x1, *hbuf, *y2;
    cudaGetSymbolAddress((void**)&qkv,  g_qkv);
    cudaGetSymbolAddress((void**)&att,  g_att);
    cudaGetSymbolAddress((void**)&y1,   g_y1);
    cudaGetSymbolAddress((void**)&x1,   g_x1);
    cudaGetSymbolAddress((void**)&hbuf, g_h);
    cudaGetSymbolAddress((void**)&y2,   g_y2);

    cudaFuncSetAttribute(attn_kernel,
                         cudaFuncAttributeMaxDynamicSharedMemorySize, ATTN_SMEM);

    const int MB = MTOT / 128;   // 64

    // fused QKV projection: x[8192,512] @ (wq|wk|wv) -> qkv[8192,1536]
    qkv_mma<<<dim3(12, MB), 256, GEMM_SMEM>>>(x, wq, bq, wk, bk, wv, bv, qkv);

    // attention
    attn_kernel<<<dim3(SEQ / AQ, BATCH * NHEAD), 256, ATTN_SMEM>>>(qkv, att);

    // output projection + residual, LN1
    gemm_mma<1><<<dim3(DIM / 128, MB), 256, GEMM_SMEM>>>(
        att, wo, DIM, bo, x, y1, DIM, DIM);
    ln_kernel<<<MTOT, 256>>>(y1, g1, be1, x1);

    // FFN
    gemm_mma<2><<<dim3(FFN / 128, MB), 256, GEMM_SMEM>>>(
        x1, w1, FFN, b1, nullptr, hbuf, FFN, DIM);
    gemm_mma<1><<<dim3(DIM / 128, MB), 256, GEMM_SMEM>>>(
        hbuf, w2, DIM, b2, x1, y2, DIM, FFN);
    ln_kernel<<<MTOT, 256>>>(y2, g2, be2, out);
}

// round 9
// speedup vs baseline: 1.5298x; 1.5298x over previous
#include <cuda_runtime.h>
#include <cuda_bf16.h>
#include <math.h>
#include <stdint.h>

// ---------------- problem constants ----------------
#define BATCH 4
#define SEQ   2048
#define DIM   512
#define NHEAD 8
#define HDIM  64
#define FFN   2048
#define MTOT  (BATCH * SEQ)          // 8192 rows
#define QKVW  (3 * DIM)              // 1536

// ---------------- scratch (no allocation allowed) ----------------
__device__ float g_qkv [MTOT * QKVW];      // fused q|k|v
__device__ float g_att [MTOT * DIM];
__device__ float g_y1  [MTOT * DIM];
__device__ float g_x1  [MTOT * DIM];
__device__ float g_h   [MTOT * FFN];
__device__ float g_y2  [MTOT * DIM];

// ---------------- helpers ----------------
__device__ __forceinline__ uint32_t f2tf(float x) {
    uint32_t r;
    asm("cvt.rna.tf32.f32 %0, %1;" : "=r"(r) : "f"(x));
    return r;
}
__device__ __forceinline__ float gelu_exact(float v) {
    return 0.5f * v * (1.0f + erff(v * 0.70710678118654752f));
}
__device__ __forceinline__ void mma16n8k8(float* c, const uint32_t* a, const uint32_t* b) {
    asm volatile(
        "mma.sync.aligned.m16n8k8.row.col.f32.tf32.tf32.f32 "
        "{%0,%1,%2,%3}, {%4,%5,%6,%7}, {%8,%9}, {%0,%1,%2,%3};"
        : "+f"(c[0]), "+f"(c[1]), "+f"(c[2]), "+f"(c[3])
        : "r"(a[0]), "r"(a[1]), "r"(a[2]), "r"(a[3]), "r"(b[0]), "r"(b[1]));
}

// ---------------- tf32 mma.sync GEMM, double-buffered pipeline ----------------
// C[128-block rows, 128-block cols] = A[M,K] @ B[K,ldb](col block) + bias (+res/gelu)
// 256 threads = 8 warps (2 x 4), warp tile 64x32, mma m16n8k8.
#define LDA 136
#define LDB 136
#define GEMM_SMEM (2 * (32 * LDA + 32 * LDB) * 4)   // 69632 bytes

template<int EPI>
__device__ __forceinline__ void mma_gemm_body(
    const float* __restrict__ A,
    const float* __restrict__ B, int ldb, int bcol,
    const float* __restrict__ biasBlk,       // pre-offset to this col block
    const float* __restrict__ res,
    float* __restrict__ C, int ldc, int ccol,
    int K)
{
    extern __shared__ uint32_t smu[];
    uint32_t* AsB = smu;                    // 2 x [32][LDA]  k-major, m fast
    uint32_t* BsB = smu + 2 * 32 * LDA;     // 2 x [32][LDB]  k-major, n fast

    const int tid  = threadIdx.x;
    const int lane = tid & 31;
    const int wid  = tid >> 5;
    const int gid  = lane >> 2;
    const int tig  = lane & 3;
    const int rowBase = blockIdx.y * 128;
    const int mb = (wid & 1) * 64;
    const int nb = (wid >> 1) * 32;

    // cooperative load mapping
    const int ar  = tid >> 1;              // 0..127  (A row in tile)
    const int akq = (tid & 1) * 16;        // 0 / 16  (A k offset)
    const int bkr = tid >> 3;              // 0..31   (B k row)
    const int bc  = (tid & 7) * 16;        // B n offset

    float acc[4][4][4];
    #pragma unroll
    for (int i = 0; i < 4; i++)
        #pragma unroll
        for (int j = 0; j < 4; j++)
            #pragma unroll
            for (int e = 0; e < 4; e++) acc[i][j][e] = 0.0f;

    const float* apB = A + (size_t)(rowBase + ar) * K + akq;
    const float* bpB = B + (size_t)bkr * ldb + bcol + bc;

    float4 arg[4], brg[4];

    // prologue: stage chunk 0
    #pragma unroll
    for (int i = 0; i < 4; i++) {
        arg[i] = *(const float4*)(apB + i * 4);
        brg[i] = *(const float4*)(bpB + i * 4);
    }
    #pragma unroll
    for (int i = 0; i < 4; i++) {
        AsB[(akq + i * 4 + 0) * LDA + ar] = f2tf(arg[i].x);
        AsB[(akq + i * 4 + 1) * LDA + ar] = f2tf(arg[i].y);
        AsB[(akq + i * 4 + 2) * LDA + ar] = f2tf(arg[i].z);
        AsB[(akq + i * 4 + 3) * LDA + ar] = f2tf(arg[i].w);
        uint4 u = make_uint4(f2tf(brg[i].x), f2tf(brg[i].y), f2tf(brg[i].z), f2tf(brg[i].w));
        *(uint4*)&BsB[bkr * LDB + bc + i * 4] = u;
    }
    __syncthreads();

    const int NC = K >> 5;
    for (int c = 0; c < NC; c++) {
        const int buf = c & 1;
        const bool more = (c + 1 < NC);

        // issue next-chunk global loads BEFORE compute (latency hides behind MMA)
        if (more) {
            const float* ap = apB + (c + 1) * 32;
            const float* bp = bpB + (size_t)((c + 1) * 32) * ldb;
            #pragma unroll
            for (int i = 0; i < 4; i++) {
                arg[i] = *(const float4*)(ap + i * 4);
                brg[i] = *(const float4*)(bp + i * 4);
            }
        }

        // compute current chunk from smem buffer `buf`
        {
            const uint32_t* As = AsB + buf * 32 * LDA;
            const uint32_t* Bs = BsB + buf * 32 * LDB;
            #pragma unroll
            for (int k8 = 0; k8 < 4; k8++) {
                const int r0 = k8 * 8 + tig;
                const int r1 = r0 + 4;
                uint32_t a[4][4], b[4][2];
                #pragma unroll
                for (int mt = 0; mt < 4; mt++) {
                    const int cm = mb + mt * 16 + gid;
                    a[mt][0] = As[r0 * LDA + cm];
                    a[mt][1] = As[r0 * LDA + cm + 8];
                    a[mt][2] = As[r1 * LDA + cm];
                    a[mt][3] = As[r1 * LDA + cm + 8];
                }
                #pragma unroll
                for (int nt = 0; nt < 4; nt++) {
                    const int cn = nb + nt * 8 + gid;
                    b[nt][0] = Bs[r0 * LDB + cn];
                    b[nt][1] = Bs[r1 * LDB + cn];
                }
                #pragma unroll
                for (int mt = 0; mt < 4; mt++)
                    #pragma unroll
                    for (int nt = 0; nt < 4; nt++)
                        mma16n8k8(acc[mt][nt], a[mt], b[nt]);
            }
        }

        // store next chunk into the alternate buffer
        if (more) {
            uint32_t* As = AsB + (buf ^ 1) * 32 * LDA;
            uint32_t* Bs = BsB + (buf ^ 1) * 32 * LDB;
            #pragma unroll
            for (int i = 0; i < 4; i++) {
                As[(akq + i * 4 + 0) * LDA + ar] = f2tf(arg[i].x);
                As[(akq + i * 4 + 1) * LDA + ar] = f2tf(arg[i].y);
                As[(akq + i * 4 + 2) * LDA + ar] = f2tf(arg[i].z);
                As[(akq + i * 4 + 3) * LDA + ar] = f2tf(arg[i].w);
                uint4 u = make_uint4(f2tf(brg[i].x), f2tf(brg[i].y),
                                     f2tf(brg[i].z), f2tf(brg[i].w));
                *(uint4*)&Bs[bkr * LDB + bc + i * 4] = u;
            }
            __syncthreads();
        }
    }

    // epilogue
    #pragma unroll
    for (int mt = 0; mt < 4; mt++) {
        const int row0 = rowBase + mb + mt * 16 + gid;
        const int row1 = row0 + 8;
        #pragma unroll
        for (int nt = 0; nt < 4; nt++) {
            const int jc  = nb + nt * 8 + tig * 2;  // local col in 128-block
            const int col = ccol + jc;
            const float b0 = biasBlk[jc], b1 = biasBlk[jc + 1];
            float v0 = acc[mt][nt][0] + b0;
            float v1 = acc[mt][nt][1] + b1;
            float v2 = acc[mt][nt][2] + b0;
            float v3 = acc[mt][nt][3] + b1;
            if (EPI == 1) {
                const float* rp0 = res + (size_t)row0 * ldc + col;
                const float* rp1 = res + (size_t)row1 * ldc + col;
                v0 += rp0[0]; v1 += rp0[1];
                v2 += rp1[0]; v3 += rp1[1];
            }
            if (EPI == 2) {
                v0 = gelu_exact(v0); v1 = gelu_exact(v1);
                v2 = gelu_exact(v2); v3 = gelu_exact(v3);
            }
            *(float2*)(C + (size_t)row0 * ldc + col) = make_float2(v0, v1);
            *(float2*)(C + (size_t)row1 * ldc + col) = make_float2(v2, v3);
        }
    }
}

template<int EPI>
__global__ __launch_bounds__(256) void gemm_mma(
    const float* __restrict__ A, const float* __restrict__ B, int ldb,
    const float* __restrict__ bias, const float* __restrict__ res,
    float* __restrict__ C, int ldc, int K)
{
    const int bcol = blockIdx.x * 128;
    mma_gemm_body<EPI>(A, B, ldb, bcol, bias + bcol, res, C, ldc, bcol, K);
}

// fused QKV: blockIdx.x in [0,12): sel = bx>>2 picks wq/wk/wv, (bx&3) picks col block
__global__ __launch_bounds__(256) void qkv_mma(
    const float* __restrict__ x,
    const float* __restrict__ wq, const float* __restrict__ bq,
    const float* __restrict__ wk, const float* __restrict__ bk,
    const float* __restrict__ wv, const float* __restrict__ bv,
    float* __restrict__ qkv)
{
    const int bx  = blockIdx.x;
    const int sel = bx >> 2;
    const float* W  = (sel == 0) ? wq : (sel == 1) ? wk : wv;
    const float* bi = (sel == 0) ? bq : (sel == 1) ? bk : bv;
    const int bcol = (bx & 3) * 128;
    mma_gemm_body<0>(x, W, DIM, bcol, bi + bcol, nullptr, qkv, QKVW, bx * 128, DIM);
}

// ---------------- flash attention (fp32), AQ=64, AK=64 ----------------
#define AQ 64
#define AK 64
#define PAD 4
#define AST (AK + PAD)   // 68

__global__ __launch_bounds__(256) void attn_kernel(
    const float* __restrict__ QKV, float* __restrict__ O)
{
    extern __shared__ float sm[];
    float* Qs = sm;                    // [HDIM][AST]
    float* Ks = Qs + HDIM * AST;       // [HDIM][AST]
    float* Vs = Ks + HDIM * AST;       // [AK][AST]
    float* Ss = Vs + AK * AST;         // [AQ][AST]
    float* mrow = Ss + AQ * AST;
    float* lrow = mrow + AQ;
    float* arow = lrow + AQ;

#define QS(d,qq) Qs[(d)*AST+(qq)]
#define KS(d,kk) Ks[(d)*AST+(kk)]
#define VS(kk,d) Vs[(kk)*AST+(d)]
#define SS(qq,kk) Ss[(qq)*AST+(kk)]

    const int tid = threadIdx.x;
    const int tx  = tid & 15;
    const int ty  = tid >> 4;
    const int lane = tid & 31;
    const int d0   = (tid >> 5) * 8;
    const int bh = blockIdx.y;
    const int b  = bh >> 3;
    const int h  = bh & 7;
    const int q0 = blockIdx.x * AQ;
    const float scale = 0.125f;
    const int LD = QKVW;               // fused qkv row stride

    const float* Qb = QKV + (size_t)b * SEQ * LD + (size_t)h * HDIM;
    const float* Kb = Qb + DIM;
    const float* Vb = Qb + 2 * DIM;

    {
        const float* p0 = Qb + (size_t)(q0 + lane) * LD + d0;
        const float* p1 = Qb + (size_t)(q0 + lane + 32) * LD + d0;
        float4 u0 = *(const float4*)p0;
        float4 u1 = *(const float4*)(p0 + 4);
        float4 u2 = *(const float4*)p1;
        float4 u3 = *(const float4*)(p1 + 4);
        QS(d0 + 0, lane) = u0.x; QS(d0 + 1, lane) = u0.y;
        QS(d0 + 2, lane) = u0.z; QS(d0 + 3, lane) = u0.w;
        QS(d0 + 4, lane) = u1.x; QS(d0 + 5, lane) = u1.y;
        QS(d0 + 6, lane) = u1.z; QS(d0 + 7, lane) = u1.w;
        QS(d0 + 0, lane + 32) = u2.x; QS(d0 + 1, lane + 32) = u2.y;
        QS(d0 + 2, lane + 32) = u2.z; QS(d0 + 3, lane + 32) = u2.w;
        QS(d0 + 4, lane + 32) = u3.x; QS(d0 + 5, lane + 32) = u3.y;
        QS(d0 + 6, lane + 32) = u3.z; QS(d0 + 7, lane + 32) = u3.w;
    }
    if (tid < AQ) { mrow[tid] = -1e30f; lrow[tid] = 0.0f; }

    float o[4][4] = {};

    for (int t = 0; t < SEQ / AK; t++) {
        __syncthreads();
        {
            const float* kp0 = Kb + (size_t)(t * AK + lane) * LD + d0;
            const float* kp1 = kp0 + (size_t)32 * LD;
            float4 k0v = *(const float4*)kp0;
            float4 k1v = *(const float4*)(kp0 + 4);
            float4 k2v = *(const float4*)kp1;
            float4 k3v = *(const float4*)(kp1 + 4);
            KS(d0 + 0, lane) = k0v.x; KS(d0 + 1, lane) = k0v.y;
            KS(d0 + 2, lane) = k0v.z; KS(d0 + 3, lane) = k0v.w;
            KS(d0 + 4, lane) = k1v.x; KS(d0 + 5, lane) = k1v.y;
            KS(d0 + 6, lane) = k1v.z; KS(d0 + 7, lane) = k1v.w;
            KS(d0 + 0, lane + 32) = k2v.x; KS(d0 + 1, lane + 32) = k2v.y;
            KS(d0 + 2, lane + 32) = k2v.z; KS(d0 + 3, lane + 32) = k2v.w;
            KS(d0 + 4, lane + 32) = k3v.x; KS(d0 + 5, lane + 32) = k3v.y;
            KS(d0 + 6, lane + 32) = k3v.z; KS(d0 + 7, lane + 32) = k3v.w;

            const float* vp0 = Vb + (size_t)(t * AK + lane) * LD + d0;
            const float* vp1 = vp0 + (size_t)32 * LD;
            float4 v0v = *(const float4*)vp0;
            float4 v1v = *(const float4*)(vp0 + 4);
            float4 v2v = *(const float4*)vp1;
            float4 v3v = *(const float4*)(vp1 + 4);
            *(float4*)&VS(lane, d0)          = v0v;
            *(float4*)&VS(lane, d0 + 4)      = v1v;
            *(float4*)&VS(lane + 32, d0)     = v2v;
            *(float4*)&VS(lane + 32, d0 + 4) = v3v;
        }
        __syncthreads();

        float s[4][4] = {};
        #pragma unroll 16
        for (int d = 0; d < HDIM; d++) {
            float4 aq = *(const float4*)&QS(d, ty * 4);
            float4 bk = *(const float4*)&KS(d, tx * 4);
            s[0][0] = fmaf(aq.x, bk.x, s[0][0]); s[0][1] = fmaf(aq.x, bk.y, s[0][1]);
            s[0][2] = fmaf(aq.x, bk.z, s[0][2]); s[0][3] = fmaf(aq.x, bk.w, s[0][3]);
            s[1][0] = fmaf(aq.y, bk.x, s[1][0]); s[1][1] = fmaf(aq.y, bk.y, s[1][1]);
            s[1][2] = fmaf(aq.y, bk.z, s[1][2]); s[1][3] = fmaf(aq.y, bk.w, s[1][3]);
            s[2][0] = fmaf(aq.z, bk.x, s[2][0]); s[2][1] = fmaf(aq.z, bk.y, s[2][1]);
            s[2][2] = fmaf(aq.z, bk.z, s[2][2]); s[2][3] = fmaf(aq.z, bk.w, s[2][3]);
            s[3][0] = fmaf(aq.w, bk.x, s[3][0]); s[3][1] = fmaf(aq.w, bk.y, s[3][1]);
            s[3][2] = fmaf(aq.w, bk.z, s[3][2]); s[3][3] = fmaf(aq.w, bk.w, s[3][3]);
        }
        #pragma unroll
        for (int i = 0; i < 4; i++) {
            float4 w = make_float4(s[i][0] * scale, s[i][1] * scale,
                                   s[i][2] * scale, s[i][3] * scale);
            *(float4*)&SS(ty * 4 + i, tx * 4) = w;
        }
        __syncthreads();

        {
            const int r = tid >> 2;
            const int p = tid & 3;
            float* row = &SS(r, p * 16);
            float4 e0 = *(float4*)(row + 0);
            float4 e1 = *(float4*)(row + 4);
            float4 e2 = *(float4*)(row + 8);
            float4 e3 = *(float4*)(row + 12);
            const float mold = mrow[r];
            float mx = fmaxf(fmaxf(fmaxf(e0.x, e0.y), fmaxf(e0.z, e0.w)),
                             fmaxf(fmaxf(e1.x, e1.y), fmaxf(e1.z, e1.w)));
            mx = fmaxf(mx, fmaxf(fmaxf(fmaxf(e2.x, e2.y), fmaxf(e2.z, e2.w)),
                                 fmaxf(fmaxf(e3.x, e3.y), fmaxf(e3.z, e3.w))));
            mx = fmaxf(mx, __shfl_xor_sync(0xffffffffu, mx, 1));
            mx = fmaxf(mx, __shfl_xor_sync(0xffffffffu, mx, 2));
            mx = fmaxf(mx, mold);
            e0.x = __expf(e0.x - mx); e0.y = __expf(e0.y - mx);
            e0.z = __expf(e0.z - mx); e0.w = __expf(e0.w - mx);
            e1.x = __expf(e1.x - mx); e1.y = __expf(e1.y - mx);
            e1.z = __expf(e1.z - mx); e1.w = __expf(e1.w - mx);
            e2.x = __expf(e2.x - mx); e2.y = __expf(e2.y - mx);
            e2.z = __expf(e2.z - mx); e2.w = __expf(e2.w - mx);
            e3.x = __expf(e3.x - mx); e3.y = __expf(e3.y - mx);
            e3.z = __expf(e3.z - mx); e3.w = __expf(e3.w - mx);
            *(float4*)(row + 0)  = e0;
            *(float4*)(row + 4)  = e1;
            *(float4*)(row + 8)  = e2;
            *(float4*)(row + 12) = e3;
            float sum = (e0.x + e0.y + e0.z + e0.w) + (e1.x + e1.y + e1.z + e1.w)
                      + (e2.x + e2.y + e2.z + e2.w) + (e3.x + e3.y + e3.z + e3.w);
            sum += __shfl_xor_sync(0xffffffffu, sum, 1);
            sum += __shfl_xor_sync(0xffffffffu, sum, 2);
            if (p == 0) {
                const float al = __expf(mold - mx);
                arow[r] = al;
                lrow[r] = lrow[r] * al + sum;
                mrow[r] = mx;
            }
        }
        __syncthreads();

        {
            const float al0 = arow[ty * 4 + 0];
            const float al1 = arow[ty * 4 + 1];
            const float al2 = arow[ty * 4 + 2];
            const float al3 = arow[ty * 4 + 3];
            #pragma unroll
            for (int j = 0; j < 4; j++) {
                o[0][j] *= al0; o[1][j] *= al1; o[2][j] *= al2; o[3][j] *= al3;
            }
            #pragma unroll 16
            for (int kk = 0; kk < AK; kk++) {
                const float a0 = SS(ty * 4 + 0, kk);
                const float a1 = SS(ty * 4 + 1, kk);
                const float a2 = SS(ty * 4 + 2, kk);
                const float a3 = SS(ty * 4 + 3, kk);
                float4 bv = *(const float4*)&VS(kk, tx * 4);
                o[0][0] = fmaf(a0, bv.x, o[0][0]); o[0][1] = fmaf(a0, bv.y, o[0][1]);
                o[0][2] = fmaf(a0, bv.z, o[0][2]); o[0][3] = fmaf(a0, bv.w, o[0][3]);
                o[1][0] = fmaf(a1, bv.x, o[1][0]); o[1][1] = fmaf(a1, bv.y, o[1][1]);
                o[1][2] = fmaf(a1, bv.z, o[1][2]); o[1][3] = fmaf(a1, bv.w, o[1][3]);
                o[2][0] = fmaf(a2, bv.x, o[2][0]); o[2][1] = fmaf(a2, bv.y, o[2][1]);
                o[2][2] = fmaf(a2, bv.z, o[2][2]); o[2][3] = fmaf(a2, bv.w, o[2][3]);
                o[3][0] = fmaf(a3, bv.x, o[3][0]); o[3][1] = fmaf(a3, bv.y, o[3][1]);
                o[3][2] = fmaf(a3, bv.z, o[3][2]); o[3][3] = fmaf(a3, bv.w, o[3][3]);
            }
        }
    }

    const float inv0 = 1.0f / lrow[ty * 4 + 0];
    const float inv1 = 1.0f / lrow[ty * 4 + 1];
    const float inv2 = 1.0f / lrow[ty * 4 + 2];
    const float inv3 = 1.0f / lrow[ty * 4 + 3];
    float* Ob = O + (size_t)b * SEQ * DIM + (size_t)h * HDIM;
    {
        float4 w0 = make_float4(o[0][0] * inv0, o[0][1] * inv0, o[0][2] * inv0, o[0][3] * inv0);
        float4 w1 = make_float4(o[1][0] * inv1, o[1][1] * inv1, o[1][2] * inv1, o[1][3] * inv1);
        float4 w2 = make_float4(o[2][0] * inv2, o[2][1] * inv2, o[2][2] * inv2, o[2][3] * inv2);
        float4 w3 = make_float4(o[3][0] * inv3, o[3][1] * inv3, o[3][2] * inv3, o[3][3] * inv3);
        *(float4*)(Ob + (size_t)(q0 + ty * 4 + 0) * DIM + tx * 4) = w0;
        *(float4*)(Ob + (size_t)(q0 + ty * 4 + 1) * DIM + tx * 4) = w1;
        *(float4*)(Ob + (size_t)(q0 + ty * 4 + 2) * DIM + tx * 4) = w2;
        *(float4*)(Ob + (size_t)(q0 + ty * 4 + 3) * DIM + tx * 4) = w3;
    }
}

#define ATTN_SMEM ((2 * HDIM * AST + AK * AST + AQ * AST + 3 * AQ) * (int)sizeof(float))

// ---------------- layernorm ----------------
__global__ __launch_bounds__(256) void ln_kernel(
    const float* __restrict__ x, const float* __restrict__ g,
    const float* __restrict__ be, float* __restrict__ out)
{
    const int row = blockIdx.x;
    const int t = threadIdx.x;
    const float* xr = x + (size_t)row * DIM;
    float v0 = xr[t], v1 = xr[t + 256];
    float s = v0 + v1, sq = v0 * v0 + v1 * v1;
    #pragma unroll
    for (int o = 16; o > 0; o >>= 1) {
        s  += __shfl_xor_sync(0xffffffffu, s, o);
        sq += __shfl_xor_sync(0xffffffffu, sq, o);
    }
    __shared__ float ps[8], pq[8];
    __shared__ float mu_s, inv_s;
    if ((t & 31) == 0) { ps[t >> 5] = s; pq[t >> 5] = sq; }
    __syncthreads();
    if (t == 0) {
        float S = 0.0f, Qq = 0.0f;
        #pragma unroll
        for (int i = 0; i < 8; i++) { S += ps[i]; Qq += pq[i]; }
        float mu = S * (1.0f / DIM);
        float var = Qq * (1.0f / DIM) - mu * mu;
        mu_s = mu;
        inv_s = rsqrtf(var + 1e-5f);
    }
    __syncthreads();
    float mu = mu_s, inv = inv_s;
    out[(size_t)row * DIM + t]       = (v0 - mu) * inv * g[t]       + be[t];
    out[(size_t)row * DIM + t + 256] = (v1 - mu) * inv * g[t + 256] + be[t + 256];
}

// ---------------- launch ----------------
extern "C" void kernel_launch(void* const* d_in, const int* in_sizes, int n_in,
                              void* d_out, int out_size)
{
    const float* x   = (const float*)d_in[0];
    const float* wq  = (const float*)d_in[1];
    const float* bq  = (const float*)d_in[2];
    const float* wk  = (const float*)d_in[3];
    const float* bk  = (const float*)d_in[4];
    const float* wv  = (const float*)d_in[5];
    const float* bv  = (const float*)d_in[6];
    const float* wo  = (const float*)d_in[7];
    const float* bo  = (const float*)d_in[8];
    const float* w1  = (const float*)d_in[9];
    const float* b1  = (const float*)d_in[10];
    const float* w2  = (const float*)d_in[11];
    const float* b2  = (const float*)d_in[12];
    const float* g1  = (const float*)d_in[13];
    const float* be1 = (const float*)d_in[14];
    const float* g2  = (const float*)d_in[15];
    const float* be2 = (const float*)d_in[16];
    float* out = (float*)d_out;

    float *qkv, *att, *y1, *x1, *hbuf, *y2;
    cudaGetSymbolAddress((void**)&qkv,  g_qkv);
    cudaGetSymbolAddress((void**)&att,  g_att);
    cudaGetSymbolAddress((void**)&y1,   g_y1);
    cudaGetSymbolAddress((void**)&x1,   g_x1);
    cudaGetSymbolAddress((void**)&hbuf, g_h);
    cudaGetSymbolAddress((void**)&y2,   g_y2);

    cudaFuncSetAttribute(attn_kernel,
                         cudaFuncAttributeMaxDynamicSharedMemorySize, ATTN_SMEM);
    cudaFuncSetAttribute(qkv_mma,
                         cudaFuncAttributeMaxDynamicSharedMemorySize, GEMM_SMEM);
    cudaFuncSetAttribute(gemm_mma<1>,
                         cudaFuncAttributeMaxDynamicSharedMemorySize, GEMM_SMEM);
    cudaFuncSetAttribute(gemm_mma<2>,
                         cudaFuncAttributeMaxDynamicSharedMemorySize, GEMM_SMEM);

    const int MB = MTOT / 128;   // 64

    // fused QKV projection: x[8192,512] @ (wq|wk|wv) -> qkv[8192,1536]
    qkv_mma<<<dim3(12, MB), 256, GEMM_SMEM>>>(x, wq, bq, wk, bk, wv, bv, qkv);

    // attention
    attn_kernel<<<dim3(SEQ / AQ, BATCH * NHEAD), 256, ATTN_SMEM>>>(qkv, att);

    // output projection + residual, LN1
    gemm_mma<1><<<dim3(DIM / 128, MB), 256, GEMM_SMEM>>>(
        att, wo, DIM, bo, x, y1, DIM, DIM);
    ln_kernel<<<MTOT, 256>>>(y1, g1, be1, x1);

    // FFN
    gemm_mma<2><<<dim3(FFN / 128, MB), 256, GEMM_SMEM>>>(
        x1, w1, FFN, b1, nullptr, hbuf, FFN, DIM);
    gemm_mma<1><<<dim3(DIM / 128, MB), 256, GEMM_SMEM>>>(
        hbuf, w2, DIM, b2, x1, y2, DIM, FFN);
    ln_kernel<<<MTOT, 256>>>(y2, g2, be2, out);
}

// round 10
// speedup vs baseline: 2.5911x; 1.6938x over previous
#include <cuda_runtime.h>
#include <cuda_bf16.h>
#include <math.h>
#include <stdint.h>

// ---------------- problem constants ----------------
#define BATCH 4
#define SEQ   2048
#define DIM   512
#define NHEAD 8
#define HDIM  64
#define FFN   2048
#define MTOT  (BATCH * SEQ)          // 8192 rows
#define QKVW  (3 * DIM)              // 1536

// ---------------- scratch (no allocation allowed) ----------------
__device__ float g_qkv [MTOT * QKVW];      // fused q|k|v
__device__ float g_att [MTOT * DIM];
__device__ float g_y1  [MTOT * DIM];
__device__ float g_x1  [MTOT * DIM];
__device__ float g_h   [MTOT * FFN];
__device__ float g_y2  [MTOT * DIM];

// ---------------- helpers ----------------
__device__ __forceinline__ uint32_t f2tf(float x) {
    uint32_t r;
    asm("cvt.rna.tf32.f32 %0, %1;" : "=r"(r) : "f"(x));
    return r;
}
__device__ __forceinline__ float gelu_exact(float v) {
    return 0.5f * v * (1.0f + erff(v * 0.70710678118654752f));
}
__device__ __forceinline__ void mma16n8k8(float* c, const uint32_t* a, const uint32_t* b) {
    asm volatile(
        "mma.sync.aligned.m16n8k8.row.col.f32.tf32.tf32.f32 "
        "{%0,%1,%2,%3}, {%4,%5,%6,%7}, {%8,%9}, {%0,%1,%2,%3};"
        : "+f"(c[0]), "+f"(c[1]), "+f"(c[2]), "+f"(c[3])
        : "r"(a[0]), "r"(a[1]), "r"(a[2]), "r"(a[3]), "r"(b[0]), "r"(b[1]));
}

// ---------------- tf32 mma.sync GEMM, double-buffered pipeline ----------------
#define LDA 136
#define LDB 136
#define GEMM_SMEM (2 * (32 * LDA + 32 * LDB) * 4)   // 69632 bytes

template<int EPI>
__device__ __forceinline__ void mma_gemm_body(
    const float* __restrict__ A,
    const float* __restrict__ B, int ldb, int bcol,
    const float* __restrict__ biasBlk,
    const float* __restrict__ res,
    float* __restrict__ C, int ldc, int ccol,
    int K)
{
    extern __shared__ uint32_t smu[];
    uint32_t* AsB = smu;
    uint32_t* BsB = smu + 2 * 32 * LDA;

    const int tid  = threadIdx.x;
    const int lane = tid & 31;
    const int wid  = tid >> 5;
    const int gid  = lane >> 2;
    const int tig  = lane & 3;
    const int rowBase = blockIdx.y * 128;
    const int mb = (wid & 1) * 64;
    const int nb = (wid >> 1) * 32;

    const int ar  = tid >> 1;
    const int akq = (tid & 1) * 16;
    const int bkr = tid >> 3;
    const int bc  = (tid & 7) * 16;

    float acc[4][4][4];
    #pragma unroll
    for (int i = 0; i < 4; i++)
        #pragma unroll
        for (int j = 0; j < 4; j++)
            #pragma unroll
            for (int e = 0; e < 4; e++) acc[i][j][e] = 0.0f;

    const float* apB = A + (size_t)(rowBase + ar) * K + akq;
    const float* bpB = B + (size_t)bkr * ldb + bcol + bc;

    float4 arg[4], brg[4];

    #pragma unroll
    for (int i = 0; i < 4; i++) {
        arg[i] = *(const float4*)(apB + i * 4);
        brg[i] = *(const float4*)(bpB + i * 4);
    }
    #pragma unroll
    for (int i = 0; i < 4; i++) {
        AsB[(akq + i * 4 + 0) * LDA + ar] = f2tf(arg[i].x);
        AsB[(akq + i * 4 + 1) * LDA + ar] = f2tf(arg[i].y);
        AsB[(akq + i * 4 + 2) * LDA + ar] = f2tf(arg[i].z);
        AsB[(akq + i * 4 + 3) * LDA + ar] = f2tf(arg[i].w);
        uint4 u = make_uint4(f2tf(brg[i].x), f2tf(brg[i].y), f2tf(brg[i].z), f2tf(brg[i].w));
        *(uint4*)&BsB[bkr * LDB + bc + i * 4] = u;
    }
    __syncthreads();

    const int NC = K >> 5;
    for (int c = 0; c < NC; c++) {
        const int buf = c & 1;
        const bool more = (c + 1 < NC);

        if (more) {
            const float* ap = apB + (c + 1) * 32;
            const float* bp = bpB + (size_t)((c + 1) * 32) * ldb;
            #pragma unroll
            for (int i = 0; i < 4; i++) {
                arg[i] = *(const float4*)(ap + i * 4);
                brg[i] = *(const float4*)(bp + i * 4);
            }
        }

        {
            const uint32_t* As = AsB + buf * 32 * LDA;
            const uint32_t* Bs = BsB + buf * 32 * LDB;
            #pragma unroll
            for (int k8 = 0; k8 < 4; k8++) {
                const int r0 = k8 * 8 + tig;
                const int r1 = r0 + 4;
                uint32_t a[4][4], b[4][2];
                #pragma unroll
                for (int mt = 0; mt < 4; mt++) {
                    const int cm = mb + mt * 16 + gid;
                    a[mt][0] = As[r0 * LDA + cm];
                    a[mt][1] = As[r0 * LDA + cm + 8];
                    a[mt][2] = As[r1 * LDA + cm];
                    a[mt][3] = As[r1 * LDA + cm + 8];
                }
                #pragma unroll
                for (int nt = 0; nt < 4; nt++) {
                    const int cn = nb + nt * 8 + gid;
                    b[nt][0] = Bs[r0 * LDB + cn];
                    b[nt][1] = Bs[r1 * LDB + cn];
                }
                #pragma unroll
                for (int mt = 0; mt < 4; mt++)
                    #pragma unroll
                    for (int nt = 0; nt < 4; nt++)
                        mma16n8k8(acc[mt][nt], a[mt], b[nt]);
            }
        }

        if (more) {
            uint32_t* As = AsB + (buf ^ 1) * 32 * LDA;
            uint32_t* Bs = BsB + (buf ^ 1) * 32 * LDB;
            #pragma unroll
            for (int i = 0; i < 4; i++) {
                As[(akq + i * 4 + 0) * LDA + ar] = f2tf(arg[i].x);
                As[(akq + i * 4 + 1) * LDA + ar] = f2tf(arg[i].y);
                As[(akq + i * 4 + 2) * LDA + ar] = f2tf(arg[i].z);
                As[(akq + i * 4 + 3) * LDA + ar] = f2tf(arg[i].w);
                uint4 u = make_uint4(f2tf(brg[i].x), f2tf(brg[i].y),
                                     f2tf(brg[i].z), f2tf(brg[i].w));
                *(uint4*)&Bs[bkr * LDB + bc + i * 4] = u;
            }
            __syncthreads();
        }
    }

    #pragma unroll
    for (int mt = 0; mt < 4; mt++) {
        const int row0 = rowBase + mb + mt * 16 + gid;
        const int row1 = row0 + 8;
        #pragma unroll
        for (int nt = 0; nt < 4; nt++) {
            const int jc  = nb + nt * 8 + tig * 2;
            const int col = ccol + jc;
            const float b0 = biasBlk[jc], b1 = biasBlk[jc + 1];
            float v0 = acc[mt][nt][0] + b0;
            float v1 = acc[mt][nt][1] + b1;
            float v2 = acc[mt][nt][2] + b0;
            float v3 = acc[mt][nt][3] + b1;
            if (EPI == 1) {
                const float* rp0 = res + (size_t)row0 * ldc + col;
                const float* rp1 = res + (size_t)row1 * ldc + col;
                v0 += rp0[0]; v1 += rp0[1];
                v2 += rp1[0]; v3 += rp1[1];
            }
            if (EPI == 2) {
                v0 = gelu_exact(v0); v1 = gelu_exact(v1);
                v2 = gelu_exact(v2); v3 = gelu_exact(v3);
            }
            *(float2*)(C + (size_t)row0 * ldc + col) = make_float2(v0, v1);
            *(float2*)(C + (size_t)row1 * ldc + col) = make_float2(v2, v3);
        }
    }
}

template<int EPI>
__global__ __launch_bounds__(256) void gemm_mma(
    const float* __restrict__ A, const float* __restrict__ B, int ldb,
    const float* __restrict__ bias, const float* __restrict__ res,
    float* __restrict__ C, int ldc, int K)
{
    const int bcol = blockIdx.x * 128;
    mma_gemm_body<EPI>(A, B, ldb, bcol, bias + bcol, res, C, ldc, bcol, K);
}

__global__ __launch_bounds__(256) void qkv_mma(
    const float* __restrict__ x,
    const float* __restrict__ wq, const float* __restrict__ bq,
    const float* __restrict__ wk, const float* __restrict__ bk,
    const float* __restrict__ wv, const float* __restrict__ bv,
    float* __restrict__ qkv)
{
    const int bx  = blockIdx.x;
    const int sel = bx >> 2;
    const float* W  = (sel == 0) ? wq : (sel == 1) ? wk : wv;
    const float* bi = (sel == 0) ? bq : (sel == 1) ? bk : bv;
    const int bcol = (bx & 3) * 128;
    mma_gemm_body<0>(x, W, DIM, bcol, bi + bcol, nullptr, qkv, QKVW, bx * 128, DIM);
}

// ---------------- tensor-core flash attention (tf32 mma) ----------------
// block: 256 thr = 8 warps; 128 queries x one (batch,head); K-blocks of 64.
// Ks [64 key][68 d] tf32 ; Vs [64 key][72 d] tf32 ; Ps [128 q][68 key] tf32
#define ALD 68
#define VLD 72
#define ATTN_SMEM ((64 * ALD + 64 * VLD + 128 * ALD) * 4)   // 70656 B

__global__ __launch_bounds__(256) void attn_tc(
    const float* __restrict__ QKV, float* __restrict__ O)
{
    extern __shared__ uint32_t asm_[];
    uint32_t* Ks = asm_;                 // [64][ALD]  [key][d]
    uint32_t* Vs = Ks + 64 * ALD;        // [64][VLD]  [key][d]
    uint32_t* Ps = Vs + 64 * VLD;        // [128][ALD] [q][key]

    const int tid  = threadIdx.x;
    const int lane = tid & 31;
    const int wid  = tid >> 5;           // 0..7
    const int gid  = lane >> 2;
    const int tig  = lane & 3;
    const int bh = blockIdx.y;
    const int b  = bh >> 3;
    const int h  = bh & 7;
    const int q0 = blockIdx.x * 128;

    const float* base = QKV + (size_t)b * SEQ * QKVW + (size_t)h * HDIM;
    const float* Qb = base;
    const float* Kb = base + DIM;
    const float* Vb = base + 2 * DIM;

    // Q fragments in registers, scale 1/8 folded in (exact)
    uint32_t qa[8][4];
    {
        const float* qr0 = Qb + (size_t)(q0 + wid * 16 + gid) * QKVW;
        const float* qr1 = qr0 + (size_t)8 * QKVW;
        #pragma unroll
        for (int ks = 0; ks < 8; ks++) {
            const int c = ks * 8 + tig;
            qa[ks][0] = f2tf(qr0[c] * 0.125f);
            qa[ks][1] = f2tf(qr1[c] * 0.125f);
            qa[ks][2] = f2tf(qr0[c + 4] * 0.125f);
            qa[ks][3] = f2tf(qr1[c + 4] * 0.125f);
        }
    }

    float o[8][4];
    #pragma unroll
    for (int i = 0; i < 8; i++)
        #pragma unroll
        for (int j = 0; j < 4; j++) o[i][j] = 0.0f;
    float m0 = -1e30f, m1 = -1e30f, l0 = 0.0f, l1 = 0.0f;

    // K/V cooperative load mapping: thread -> key row tid>>2, 16 floats
    const int kr = tid >> 2;
    const int dc = (tid & 3) * 16;
    const size_t KVSTEP = (size_t)64 * QKVW;
    const float* kp = Kb + (size_t)kr * QKVW + dc;
    const float* vp = Vb + (size_t)kr * QKVW + dc;

    float4 krg[4], vrg[4];
    #pragma unroll
    for (int i = 0; i < 4; i++) {
        krg[i] = *(const float4*)(kp + i * 4);
        vrg[i] = *(const float4*)(vp + i * 4);
    }

    uint32_t* Pw = Ps + (wid * 16) * ALD;   // warp-private strip

    for (int t = 0; t < SEQ / 64; t++) {
        // store staged K/V to smem (tf32)
        #pragma unroll
        for (int i = 0; i < 4; i++) {
            uint4 ku = make_uint4(f2tf(krg[i].x), f2tf(krg[i].y), f2tf(krg[i].z), f2tf(krg[i].w));
            uint4 vu = make_uint4(f2tf(vrg[i].x), f2tf(vrg[i].y), f2tf(vrg[i].z), f2tf(vrg[i].w));
            *(uint4*)&Ks[kr * ALD + dc + i * 4] = ku;
            *(uint4*)&Vs[kr * VLD + dc + i * 4] = vu;
        }
        __syncthreads();

        const bool more = (t + 1 < SEQ / 64);
        if (more) {   // prefetch next K during S-mma
            kp += KVSTEP;
            #pragma unroll
            for (int i = 0; i < 4; i++) krg[i] = *(const float4*)(kp + i * 4);
        }

        // S = Q @ K^T  (k = d, n = keys)
        float s[8][4];
        #pragma unroll
        for (int i = 0; i < 8; i++)
            #pragma unroll
            for (int j = 0; j < 4; j++) s[i][j] = 0.0f;
        #pragma unroll
        for (int ks = 0; ks < 8; ks++) {
            const int d = ks * 8 + tig;
            #pragma unroll
            for (int nt = 0; nt < 8; nt++) {
                const int key = nt * 8 + gid;
                uint32_t bf[2] = { Ks[key * ALD + d], Ks[key * ALD + d + 4] };
                mma16n8k8(s[nt], qa[ks], bf);
            }
        }

        // online softmax in registers (rows r0 = wid*16+gid, r1 = +8)
        float cm0 = -1e30f, cm1 = -1e30f;
        #pragma unroll
        for (int nt = 0; nt < 8; nt++) {
            cm0 = fmaxf(cm0, fmaxf(s[nt][0], s[nt][1]));
            cm1 = fmaxf(cm1, fmaxf(s[nt][2], s[nt][3]));
        }
        cm0 = fmaxf(cm0, __shfl_xor_sync(0xffffffffu, cm0, 1));
        cm0 = fmaxf(cm0, __shfl_xor_sync(0xffffffffu, cm0, 2));
        cm1 = fmaxf(cm1, __shfl_xor_sync(0xffffffffu, cm1, 1));
        cm1 = fmaxf(cm1, __shfl_xor_sync(0xffffffffu, cm1, 2));
        const float mn0 = fmaxf(m0, cm0);
        const float mn1 = fmaxf(m1, cm1);
        const float a0 = __expf(m0 - mn0);
        const float a1 = __expf(m1 - mn1);
        float ls0 = 0.0f, ls1 = 0.0f;
        #pragma unroll
        for (int nt = 0; nt < 8; nt++) {
            s[nt][0] = __expf(s[nt][0] - mn0);
            s[nt][1] = __expf(s[nt][1] - mn0);
            s[nt][2] = __expf(s[nt][2] - mn1);
            s[nt][3] = __expf(s[nt][3] - mn1);
            ls0 += s[nt][0] + s[nt][1];
            ls1 += s[nt][2] + s[nt][3];
        }
        ls0 += __shfl_xor_sync(0xffffffffu, ls0, 1);
        ls0 += __shfl_xor_sync(0xffffffffu, ls0, 2);
        ls1 += __shfl_xor_sync(0xffffffffu, ls1, 1);
        ls1 += __shfl_xor_sync(0xffffffffu, ls1, 2);
        l0 = l0 * a0 + ls0;
        l1 = l1 * a1 + ls1;
        m0 = mn0; m1 = mn1;
        #pragma unroll
        for (int nt = 0; nt < 8; nt++) {
            o[nt][0] *= a0; o[nt][1] *= a0;
            o[nt][2] *= a1; o[nt][3] *= a1;
        }

        if (more) {   // prefetch next V during P-store / PV-mma
            vp += KVSTEP;
            #pragma unroll
            for (int i = 0; i < 4; i++) vrg[i] = *(const float4*)(vp + i * 4);
        }

        // store P (tf32) to warp-private smem strip
        #pragma unroll
        for (int nt = 0; nt < 8; nt++) {
            const int c = nt * 8 + tig * 2;
            *(uint2*)&Pw[gid * ALD + c]       = make_uint2(f2tf(s[nt][0]), f2tf(s[nt][1]));
            *(uint2*)&Pw[(gid + 8) * ALD + c] = make_uint2(f2tf(s[nt][2]), f2tf(s[nt][3]));
        }
        __syncwarp();

        // O += P @ V  (k = keys, n = d)
        #pragma unroll
        for (int ks = 0; ks < 8; ks++) {
            const int kk = ks * 8 + tig;
            uint32_t pa[4];
            pa[0] = Pw[gid * ALD + kk];
            pa[1] = Pw[(gid + 8) * ALD + kk];
            pa[2] = Pw[gid * ALD + kk + 4];
            pa[3] = Pw[(gid + 8) * ALD + kk + 4];
            #pragma unroll
            for (int nt = 0; nt < 8; nt++) {
                const int dn = nt * 8 + gid;
                uint32_t bf[2] = { Vs[kk * VLD + dn], Vs[(kk + 4) * VLD + dn] };
                mma16n8k8(o[nt], pa, bf);
            }
        }
        __syncthreads();   // all warps done with Ks/Vs before next overwrite
    }

    // normalize and write out: att[row][DIM], col = h*64 + ...
    const float i0 = 1.0f / l0;
    const float i1 = 1.0f / l1;
    const int row0 = q0 + wid * 16 + gid;
    float* Ob0 = O + (size_t)(b * SEQ + row0) * DIM + h * HDIM;
    float* Ob1 = Ob0 + (size_t)8 * DIM;
    #pragma unroll
    for (int nt = 0; nt < 8; nt++) {
        const int c = nt * 8 + tig * 2;
        *(float2*)(Ob0 + c) = make_float2(o[nt][0] * i0, o[nt][1] * i0);
        *(float2*)(Ob1 + c) = make_float2(o[nt][2] * i1, o[nt][3] * i1);
    }
}

// ---------------- layernorm ----------------
__global__ __launch_bounds__(256) void ln_kernel(
    const float* __restrict__ x, const float* __restrict__ g,
    const float* __restrict__ be, float* __restrict__ out)
{
    const int row = blockIdx.x;
    const int t = threadIdx.x;
    const float* xr = x + (size_t)row * DIM;
    float v0 = xr[t], v1 = xr[t + 256];
    float s = v0 + v1, sq = v0 * v0 + v1 * v1;
    #pragma unroll
    for (int o = 16; o > 0; o >>= 1) {
        s  += __shfl_xor_sync(0xffffffffu, s, o);
        sq += __shfl_xor_sync(0xffffffffu, sq, o);
    }
    __shared__ float ps[8], pq[8];
    __shared__ float mu_s, inv_s;
    if ((t & 31) == 0) { ps[t >> 5] = s; pq[t >> 5] = sq; }
    __syncthreads();
    if (t == 0) {
        float S = 0.0f, Qq = 0.0f;
        #pragma unroll
        for (int i = 0; i < 8; i++) { S += ps[i]; Qq += pq[i]; }
        float mu = S * (1.0f / DIM);
        float var = Qq * (1.0f / DIM) - mu * mu;
        mu_s = mu;
        inv_s = rsqrtf(var + 1e-5f);
    }
    __syncthreads();
    float mu = mu_s, inv = inv_s;
    out[(size_t)row * DIM + t]       = (v0 - mu) * inv * g[t]       + be[t];
    out[(size_t)row * DIM + t + 256] = (v1 - mu) * inv * g[t + 256] + be[t + 256];
}

// ---------------- launch ----------------
extern "C" void kernel_launch(void* const* d_in, const int* in_sizes, int n_in,
                              void* d_out, int out_size)
{
    const float* x   = (const float*)d_in[0];
    const float* wq  = (const float*)d_in[1];
    const float* bq  = (const float*)d_in[2];
    const float* wk  = (const float*)d_in[3];
    const float* bk  = (const float*)d_in[4];
    const float* wv  = (const float*)d_in[5];
    const float* bv  = (const float*)d_in[6];
    const float* wo  = (const float*)d_in[7];
    const float* bo  = (const float*)d_in[8];
    const float* w1  = (const float*)d_in[9];
    const float* b1  = (const float*)d_in[10];
    const float* w2  = (const float*)d_in[11];
    const float* b2  = (const float*)d_in[12];
    const float* g1  = (const float*)d_in[13];
    const float* be1 = (const float*)d_in[14];
    const float* g2  = (const float*)d_in[15];
    const float* be2 = (const float*)d_in[16];
    float* out = (float*)d_out;

    float *qkv, *att, *y1, *x1, *hbuf, *y2;
    cudaGetSymbolAddress((void**)&qkv,  g_qkv);
    cudaGetSymbolAddress((void**)&att,  g_att);
    cudaGetSymbolAddress((void**)&y1,   g_y1);
    cudaGetSymbolAddress((void**)&x1,   g_x1);
    cudaGetSymbolAddress((void**)&hbuf, g_h);
    cudaGetSymbolAddress((void**)&y2,   g_y2);

    cudaFuncSetAttribute(attn_tc,
                         cudaFuncAttributeMaxDynamicSharedMemorySize, ATTN_SMEM);
    cudaFuncSetAttribute(qkv_mma,
                         cudaFuncAttributeMaxDynamicSharedMemorySize, GEMM_SMEM);
    cudaFuncSetAttribute(gemm_mma<1>,
                         cudaFuncAttributeMaxDynamicSharedMemorySize, GEMM_SMEM);
    cudaFuncSetAttribute(gemm_mma<2>,
                         cudaFuncAttributeMaxDynamicSharedMemorySize, GEMM_SMEM);

    const int MB = MTOT / 128;   // 64

    // fused QKV projection
    qkv_mma<<<dim3(12, MB), 256, GEMM_SMEM>>>(x, wq, bq, wk, bk, wv, bv, qkv);

    // tensor-core flash attention
    attn_tc<<<dim3(SEQ / 128, BATCH * NHEAD), 256, ATTN_SMEM>>>(qkv, att);

    // output projection + residual, LN1
    gemm_mma<1><<<dim3(DIM / 128, MB), 256, GEMM_SMEM>>>(
        att, wo, DIM, bo, x, y1, DIM, DIM);
    ln_kernel<<<MTOT, 256>>>(y1, g1, be1, x1);

    // FFN
    gemm_mma<2><<<dim3(FFN / 128, MB), 256, GEMM_SMEM>>>(
        x1, w1, FFN, b1, nullptr, hbuf, FFN, DIM);
    gemm_mma<1><<<dim3(DIM / 128, MB), 256, GEMM_SMEM>>>(
        hbuf, w2, DIM, b2, x1, y2, DIM, FFN);
    ln_kernel<<<MTOT, 256>>>(y2, g2, be2, out);
}